// round 16
// baseline (speedup 1.0000x reference)
#include <cuda_runtime.h>
#include <stdint.h>

#define DIM_IN 16
#define CH 128
#define DIM_OUT 99
#define MAX_NNZ 512
#define MAX_PADDED 1280
#define NGROUPS ((DIM_OUT + 3) / 4)   // 25 groups of 4 rows
#define EPB 2
#define THREADS (EPB * 64)

// 16-byte term (ulonglong2): .x = ox | (oy<<16) in low 32 (u16 byte offsets
// into the 8 KB row block), .y = {cg, cg} pre-packed for f32x2 FMA.
// group (uint2): .x = kG | (n<<16) | (rowA<<24) ; .y = rowB|(rowC<<8)|(rowD<<16)
struct __align__(16) CMeta {
    ulonglong2 terms[MAX_PADDED];
    uint2      groups[NGROUPS];
};
__device__    CMeta g_meta;
__constant__  CMeta c_meta;

// ---------------------------------------------------------------------------
// Prep: fully parallel. Stable CSR sort by mu3 via rank-scatter, rows ordered
// by count desc (parallel rank), groups of 4 rows zero-padded to the group
// max ROUNDED UP TO EVEN (uniform double-step in the main kernel).
// ---------------------------------------------------------------------------
__global__ void prep_kernel(const int* __restrict__ mu1,
                            const int* __restrict__ mu2,
                            const int* __restrict__ mu3,
                            const float* __restrict__ cg,
                            int nnz)
{
    __shared__ int   sm3[MAX_NNZ];
    __shared__ uint2 st8[MAX_NNZ];       // CSR-sorted compact terms
    __shared__ int   start[DIM_OUT + 1];
    __shared__ int   cnt[DIM_OUT];
    __shared__ int   order[DIM_OUT];
    __shared__ int   gk[NGROUPS], gn[NGROUPS];
    int t = threadIdx.x;

    if (t < DIM_OUT) cnt[t] = 0;
    __syncthreads();

    for (int k = t; k < nnz; k += blockDim.x) {
        int m = mu3[k];
        sm3[k] = m;
        atomicAdd(&cnt[m], 1);
    }
    __syncthreads();

    // parallel start prefix (independent pipelined LDS per thread)
    if (t <= DIM_OUT) {
        int s = 0;
        for (int r = 0; r < t; r++) s += cnt[r];
        start[t] = s;
    }
    // parallel rank: rows ordered by (count desc, row id asc)
    if (t < DIM_OUT) {
        int c = cnt[t];
        int rk = 0;
        for (int r = 0; r < DIM_OUT; r++) {
            int cr = cnt[r];
            rk += (cr > c) || (cr == c && r < t);
        }
        order[rk] = t;
    }
    __syncthreads();

    // stable scatter into CSR (rank = #earlier terms with same mu3)
    for (int k = t; k < nnz; k += blockDim.x) {
        int m = sm3[k];
        int rank = 0;
        for (int j = 0; j < k; j++) rank += (sm3[j] == m);
        unsigned int ox = (unsigned int)mu1[k] * (CH * 4u);
        unsigned int oy = (unsigned int)mu2[k] * (CH * 4u);
        uint2 tm;
        tm.x = ox | (oy << 16);
        tm.y = __float_as_uint(cg[k]);
        st8[start[m] + rank] = tm;
    }
    // parallel group build; stream length = group max count rounded to even
    if (t < NGROUPS) {
        int i0 = 4 * t;
        int n  = (cnt[order[i0]] + 1) & ~1;
        int base = 0;
        for (int g2 = 0; g2 < t; g2++)
            base += (cnt[order[4 * g2]] + 1) & ~1;
        base *= 4;
        gk[t] = base;
        gn[t] = n;
        int rA = order[i0];
        int rB = order[(i0 + 1 < DIM_OUT) ? i0 + 1 : DIM_OUT - 1];
        int rC = order[(i0 + 2 < DIM_OUT) ? i0 + 2 : DIM_OUT - 1];
        int rD = order[(i0 + 3 < DIM_OUT) ? i0 + 3 : DIM_OUT - 1];
        uint2 gd;
        gd.x = (unsigned int)base | ((unsigned int)n << 16)
             | ((unsigned int)rA << 24);
        gd.y = (unsigned int)rB | ((unsigned int)rC << 8)
             | ((unsigned int)rD << 16);
        g_meta.groups[t] = gd;
    }
    __syncthreads();

    // parallel emit of padded 16-byte term streams (one thread per row slot)
    for (int i = t; i < 4 * NGROUPS; i += blockDim.x) {
        int g = i >> 2;
        int s = i & 3;
        int oi = (i < DIM_OUT) ? i : DIM_OUT - 1;
        int row = order[oi];
        int n   = gn[g];
        int kS  = gk[g] + s * n;
        int sR = start[row], cR = cnt[row];
        for (int j = 0; j < n; j++) {
            ulonglong2 e;
            if (j < cR) {
                uint2 tm = st8[sR + j];
                e.x = (unsigned long long)tm.x;
                e.y = ((unsigned long long)tm.y << 32) | (unsigned long long)tm.y;
            } else {
                e.x = 0ull;
                e.y = 0ull;      // cg = {+0,+0}: exact no-op FMA
            }
            g_meta.terms[kS + j] = e;
        }
    }
}

// helper: one stream step = LDS x/y for a term
#define TP_LOADS(tm, xv, yv)                                                  \
    {                                                                         \
        unsigned int mm = (unsigned int)(tm).x;                               \
        xv = *(const unsigned long long*)(sxb + (mm & 0xFFFFu));              \
        yv = *(const unsigned long long*)(syb + (mm >> 16));                  \
    }
#define TP_MATH(tm, xv, yv, acc)                                              \
    {                                                                         \
        unsigned long long p_;                                                \
        asm("mul.rn.f32x2 %0, %1, %2;" : "=l"(p_) : "l"(xv), "l"(yv));        \
        asm("fma.rn.f32x2 %0, %1, %2, %3;"                                    \
            : "=l"(acc) : "l"(p_), "l"((tm).y), "l"(acc));                    \
    }

// ---------------------------------------------------------------------------
// Main: 2 edges per 128-thread block; 64 threads/edge, one channel pair per
// thread, packed f32x2. FOUR output rows as interleaved streams, inner loop
// hand-pipelined in steps of 2 (8 term LDC + 16 LDS issued before the 16 FP
// ops). Terms from constant memory. Each real output element written once.
// ---------------------------------------------------------------------------
__global__ __launch_bounds__(THREADS, 5)
void tp_kernel(const float* __restrict__ x,
               const float* __restrict__ y,
               float* __restrict__ out)
{
    __shared__ __align__(16) float sx[EPB * DIM_IN * CH];   // 16 KB
    __shared__ __align__(16) float sy[EPB * DIM_IN * CH];   // 16 KB

    const int t    = threadIdx.x;
    const int sub  = t >> 6;
    const int lane = t & 63;
    const long long ebase = (long long)blockIdx.x * EPB;

    const float4* x4 = (const float4*)(x + ebase * (DIM_IN * CH));
    const float4* y4 = (const float4*)(y + ebase * (DIM_IN * CH));
#pragma unroll
    for (int i = 0; i < (EPB * DIM_IN * CH / 4) / THREADS; i++) {
        ((float4*)sx)[t + i * THREADS] = x4[t + i * THREADS];
        ((float4*)sy)[t + i * THREADS] = y4[t + i * THREADS];
    }
    __syncthreads();

    const char* sxb = (const char*)(sx + sub * (DIM_IN * CH)) + lane * 8;
    const char* syb = (const char*)(sy + sub * (DIM_IN * CH)) + lane * 8;
    float* outb = out + (ebase + sub) * (DIM_OUT * CH) + lane * 2;

#pragma unroll 1
    for (int g = 0; g < NGROUPS; g++) {
        uint2 gd = c_meta.groups[g];
        const int kG = gd.x & 0xFFFFu;
        const int n  = (gd.x >> 16) & 0xFFu;   // even by construction
        const int oA = gd.x >> 24;
        const int oB = gd.y & 0xFFu;
        const int oC = (gd.y >> 8) & 0xFFu;
        const int oD = (gd.y >> 16) & 0xFFu;

        const ulonglong2* tA = c_meta.terms + kG;
        const ulonglong2* tB = tA + n;
        const ulonglong2* tC = tB + n;
        const ulonglong2* tD = tC + n;

        unsigned long long accA = 0ull, accB = 0ull;
        unsigned long long accC = 0ull, accD = 0ull;
#pragma unroll 2
        for (int j = 0; j < n; j += 2) {
            // ---- issue all loads for both steps first ----
            ulonglong2 ta0 = tA[j],     tb0 = tB[j];
            ulonglong2 tc0 = tC[j],     td0 = tD[j];
            ulonglong2 ta1 = tA[j + 1], tb1 = tB[j + 1];
            ulonglong2 tc1 = tC[j + 1], td1 = tD[j + 1];
            unsigned long long xa0, ya0, xb0, yb0, xc0, yc0, xd0, yd0;
            unsigned long long xa1, ya1, xb1, yb1, xc1, yc1, xd1, yd1;
            TP_LOADS(ta0, xa0, ya0)
            TP_LOADS(tb0, xb0, yb0)
            TP_LOADS(tc0, xc0, yc0)
            TP_LOADS(td0, xd0, yd0)
            TP_LOADS(ta1, xa1, ya1)
            TP_LOADS(tb1, xb1, yb1)
            TP_LOADS(tc1, xc1, yc1)
            TP_LOADS(td1, xd1, yd1)
            // ---- then all math ----
            TP_MATH(ta0, xa0, ya0, accA)
            TP_MATH(tb0, xb0, yb0, accB)
            TP_MATH(tc0, xc0, yc0, accC)
            TP_MATH(td0, xd0, yd0, accD)
            TP_MATH(ta1, xa1, ya1, accA)
            TP_MATH(tb1, xb1, yb1, accB)
            TP_MATH(tc1, xc1, yc1, accC)
            TP_MATH(td1, xd1, yd1, accD)
        }
        *(unsigned long long*)(outb + oA * CH) = accA;
        *(unsigned long long*)(outb + oB * CH) = accB;
        *(unsigned long long*)(outb + oC * CH) = accC;
        *(unsigned long long*)(outb + oD * CH) = accD;
    }
}

// ---------------------------------------------------------------------------
// Inputs (metadata order): x f32 [N,16,128], y f32 [N,16,128],
//                          mu1 i32 [nnz], mu2 i32 [nnz], mu3 i32 [nnz], cg f32 [nnz]
// Output: f32 [N,99,128]
// ---------------------------------------------------------------------------
extern "C" void kernel_launch(void* const* d_in, const int* in_sizes, int n_in,
                              void* d_out, int out_size)
{
    const float* x   = (const float*)d_in[0];
    const float* y   = (const float*)d_in[1];
    const int*   mu1 = (const int*)d_in[2];
    const int*   mu2 = (const int*)d_in[3];
    const int*   mu3 = (const int*)d_in[4];
    const float* cg  = (const float*)d_in[5];

    int nnz = in_sizes[2];
    if (nnz > MAX_NNZ) nnz = MAX_NNZ;   // capacity guard (actual nnz ~350)
    int N = in_sizes[0] / (DIM_IN * CH);
    int nBlocks = (N + EPB - 1) / EPB;

    prep_kernel<<<1, 1024>>>(mu1, mu2, mu3, cg, nnz);

    // single D2D copy of all prepared metadata into constant memory
    void* gm_addr = nullptr;
    cudaGetSymbolAddress(&gm_addr, g_meta);
    cudaMemcpyToSymbolAsync(c_meta, gm_addr, sizeof(CMeta), 0,
                            cudaMemcpyDeviceToDevice, 0);

    tp_kernel<<<nBlocks, THREADS>>>(x, y, (float*)d_out);
}